// round 2
// baseline (speedup 1.0000x reference)
#include <cuda_runtime.h>
#include <cstddef>

#define BSZ   40
#define TSZ   20
#define FEAD  200
#define HDIM  1024
#define OUTD  1095
#define LNUM  12
#define MROWS (BSZ * TSZ)          // 800
#define OUT_ELEMS (MROWS * OUTD)   // 876000

// Scratch (no cudaMalloc allowed)
__device__ __align__(16) float g_xt[MROWS * FEAD];      // x transposed to time-major [t*B+b, FEA]
__device__ __align__(16) float g_h [MROWS * HDIM];      // layer io, time-major
__device__ __align__(16) float g_U [MROWS * 3 * HDIM];  // SRU pre-activations
__device__ __align__(16) float g_h2[MROWS * HDIM];      // batch-major after GEMM3

// ---------------------------------------------------------------------------
// x [B,T,FEA] -> xt [T*B, FEA]  (row m = t*B + b)
// ---------------------------------------------------------------------------
__global__ void transpose_x_kernel(const float* __restrict__ x, float* __restrict__ xt) {
    int idx = blockIdx.x * blockDim.x + threadIdx.x;
    if (idx >= MROWS * FEAD) return;
    int f = idx % FEAD;
    int m = idx / FEAD;
    int b = m % BSZ;
    int t = m / BSZ;
    xt[idx] = x[((size_t)b * TSZ + t) * FEAD + f];
}

// ---------------------------------------------------------------------------
// Tiled SGEMM: C[M,N] = A[M,K] @ W[K,N] (+bias) (+relu) (+output row remap)
// BM=BN=64, BK=16, 256 threads, 4x4 micro-tile per thread.
// REMAP: A rows are time-major (m = t*B+b); write C row = b*T+t (batch-major).
// ---------------------------------------------------------------------------
template<int RELU, int REMAP>
__global__ __launch_bounds__(256)
void gemm_kernel(const float* __restrict__ A, const float* __restrict__ W,
                 const float* __restrict__ bias, float* __restrict__ C,
                 int M, int K, int N) {
    __shared__ __align__(16) float As[64][20];  // [row][k] pad to 20 floats
    __shared__ __align__(16) float Bs[16][68];  // [k][col] pad to 68 floats

    const int tid = threadIdx.x;
    const int tx = tid & 15;   // 0..15 -> N
    const int ty = tid >> 4;   // 0..15 -> M
    const int row0 = blockIdx.y * 64;
    const int col0 = blockIdx.x * 64;

    // A load mapping: 64 rows x 16 k, 4 consecutive k-elems per thread
    const int aRow = tid >> 2;         // 0..63
    const int aCol = (tid & 3) << 2;   // 0,4,8,12
    // B load mapping: 16 k x 64 cols, 4 consecutive cols per thread
    const int bRow = tid >> 4;         // 0..15
    const int bCol = (tid & 15) << 2;  // 0..60

    float acc[4][4];
    #pragma unroll
    for (int i = 0; i < 4; i++)
        #pragma unroll
        for (int j = 0; j < 4; j++) acc[i][j] = 0.0f;

    const bool k_vec_ok = ((K & 3) == 0);
    const bool n_vec_ok = ((N & 3) == 0);

    for (int k0 = 0; k0 < K; k0 += 16) {
        // Load A tile
        {
            int gr = row0 + aRow;
            int gc = k0 + aCol;
            if (gr < M && gc + 3 < K && k_vec_ok) {
                float4 v = *reinterpret_cast<const float4*>(A + (size_t)gr * K + gc);
                As[aRow][aCol + 0] = v.x;
                As[aRow][aCol + 1] = v.y;
                As[aRow][aCol + 2] = v.z;
                As[aRow][aCol + 3] = v.w;
            } else {
                #pragma unroll
                for (int i = 0; i < 4; i++) {
                    As[aRow][aCol + i] =
                        (gr < M && (gc + i) < K) ? A[(size_t)gr * K + gc + i] : 0.0f;
                }
            }
        }
        // Load B tile
        {
            int gk = k0 + bRow;
            int gc = col0 + bCol;
            if (gk < K && gc + 3 < N && n_vec_ok) {
                float4 v = *reinterpret_cast<const float4*>(W + (size_t)gk * N + gc);
                Bs[bRow][bCol + 0] = v.x;
                Bs[bRow][bCol + 1] = v.y;
                Bs[bRow][bCol + 2] = v.z;
                Bs[bRow][bCol + 3] = v.w;
            } else {
                #pragma unroll
                for (int j = 0; j < 4; j++) {
                    Bs[bRow][bCol + j] =
                        (gk < K && (gc + j) < N) ? W[(size_t)gk * N + gc + j] : 0.0f;
                }
            }
        }
        __syncthreads();

        #pragma unroll
        for (int k = 0; k < 16; k++) {
            float a0 = As[ty * 4 + 0][k];
            float a1 = As[ty * 4 + 1][k];
            float a2 = As[ty * 4 + 2][k];
            float a3 = As[ty * 4 + 3][k];
            float4 bv = *reinterpret_cast<const float4*>(&Bs[k][tx * 4]);
            acc[0][0] += a0 * bv.x; acc[0][1] += a0 * bv.y; acc[0][2] += a0 * bv.z; acc[0][3] += a0 * bv.w;
            acc[1][0] += a1 * bv.x; acc[1][1] += a1 * bv.y; acc[1][2] += a1 * bv.z; acc[1][3] += a1 * bv.w;
            acc[2][0] += a2 * bv.x; acc[2][1] += a2 * bv.y; acc[2][2] += a2 * bv.z; acc[2][3] += a2 * bv.w;
            acc[3][0] += a3 * bv.x; acc[3][1] += a3 * bv.y; acc[3][2] += a3 * bv.z; acc[3][3] += a3 * bv.w;
        }
        __syncthreads();
    }

    // Epilogue
    #pragma unroll
    for (int i = 0; i < 4; i++) {
        int row = row0 + ty * 4 + i;
        if (row >= M) continue;
        int orow = row;
        if (REMAP) {
            int b = row % BSZ;
            int t = row / BSZ;
            orow = b * TSZ + t;
        }
        #pragma unroll
        for (int j = 0; j < 4; j++) {
            int col = col0 + tx * 4 + j;
            if (col >= N) continue;
            float v = acc[i][j];
            if (bias) v += bias[col];
            if (RELU) v = fmaxf(v, 0.0f);
            C[(size_t)orow * N + col] = v;
        }
    }
}

// ---------------------------------------------------------------------------
// SRU recurrence for one layer. One thread per (b, h).
// U: [T*B, 3H] time-major -> [x_tilde | uf | ur]
// h: [T*B, H] time-major, updated in place: h' = r*tanh(c) + (1-r)*h
// c_out: [B, H] final cell state (written into d_out tail)
// ---------------------------------------------------------------------------
__global__ __launch_bounds__(256)
void sru_scan_kernel(const float* __restrict__ U, const float* __restrict__ c0,
                     const float* __restrict__ sb, float* __restrict__ h,
                     float* __restrict__ c_out) {
    int idx = blockIdx.x * blockDim.x + threadIdx.x;
    if (idx >= BSZ * HDIM) return;
    int hh = idx % HDIM;
    int b  = idx / HDIM;
    float c  = c0[idx];
    float bf = sb[hh];
    float br = sb[HDIM + hh];
    #pragma unroll 4
    for (int t = 0; t < TSZ; t++) {
        size_t row = (size_t)t * BSZ + b;
        const float* Ur = U + row * (3 * HDIM);
        float xt = Ur[hh];
        float f  = 1.0f / (1.0f + __expf(-(Ur[HDIM     + hh] + bf)));
        float r  = 1.0f / (1.0f + __expf(-(Ur[2 * HDIM + hh] + br)));
        c = f * c + (1.0f - f) * xt;
        size_t hidx = row * HDIM + hh;
        float hin = h[hidx];
        h[hidx] = r * tanhf(c) + (1.0f - r) * hin;
    }
    c_out[idx] = c;
}

// ---------------------------------------------------------------------------
extern "C" void kernel_launch(void* const* d_in, const int* in_sizes, int n_in,
                              void* d_out, int out_size) {
    const float* x      = (const float*)d_in[0];
    const float* hidden = (const float*)d_in[1];
    const float* W1     = (const float*)d_in[2];
    const float* b1     = (const float*)d_in[3];
    const float* sru_W  = (const float*)d_in[4];
    const float* sru_b  = (const float*)d_in[5];
    const float* W3     = (const float*)d_in[6];
    const float* b3     = (const float*)d_in[7];
    const float* W4     = (const float*)d_in[8];
    const float* b4     = (const float*)d_in[9];
    float* out = (float*)d_out;

    float *xt, *h, *U, *h2;
    cudaGetSymbolAddress((void**)&xt, g_xt);
    cudaGetSymbolAddress((void**)&h,  g_h);
    cudaGetSymbolAddress((void**)&U,  g_U);
    cudaGetSymbolAddress((void**)&h2, g_h2);

    // 1. transpose x to time-major
    transpose_x_kernel<<<(MROWS * FEAD + 255) / 256, 256>>>(x, xt);

    // 2. dense layer 1: h = xt @ W1 + b1   (M=800, K=200, N=1024)
    {
        dim3 grid((HDIM + 63) / 64, (MROWS + 63) / 64);
        gemm_kernel<0, 0><<<grid, 256>>>(xt, W1, b1, h, MROWS, FEAD, HDIM);
    }

    // 3. SRU layers
    for (int l = 0; l < LNUM; l++) {
        dim3 gridU((3 * HDIM + 63) / 64, (MROWS + 63) / 64);
        gemm_kernel<0, 0><<<gridU, 256>>>(h, sru_W + (size_t)l * HDIM * 3 * HDIM,
                                          nullptr, U, MROWS, HDIM, 3 * HDIM);
        sru_scan_kernel<<<(BSZ * HDIM + 255) / 256, 256>>>(
            U, hidden + (size_t)l * BSZ * HDIM, sru_b + (size_t)l * 2 * HDIM, h,
            out + OUT_ELEMS + (size_t)l * BSZ * HDIM);
    }

    // 4. dense ReLU, remapping rows from time-major to batch-major
    {
        dim3 grid((HDIM + 63) / 64, (MROWS + 63) / 64);
        gemm_kernel<1, 1><<<grid, 256>>>(h, W3, b3, h2, MROWS, HDIM, HDIM);
    }

    // 5. output projection: out = h2 @ W4 + b4
    {
        dim3 grid((OUTD + 63) / 64, (MROWS + 63) / 64);
        gemm_kernel<0, 0><<<grid, 256>>>(h2, W4, b4, out, MROWS, HDIM, OUTD);
    }
}

// round 4
// speedup vs baseline: 2.3126x; 2.3126x over previous
#include <cuda_runtime.h>
#include <cuda_bf16.h>
#include <cstdint>
#include <cstddef>

#define BSZ   40
#define TSZ   20
#define FEAD  200
#define HDIM  1024
#define OUTD  1095
#define LNUM  12
#define MROWS (BSZ * TSZ)          // 800
#define OUT_ELEMS (MROWS * OUTD)   // 876000

// Weight-split region offsets (element counts)
#define OFF_W1  0
#define N_W1    (FEAD * HDIM)                  // 204800
#define OFF_SRU (OFF_W1 + N_W1)                // 204800
#define N_SRU   (LNUM * HDIM * 3 * HDIM)       // 37748736
#define OFF_W3  (OFF_SRU + N_SRU)              // 37953536
#define N_W3    (HDIM * HDIM)                  // 1048576
#define OFF_W4  (OFF_W3 + N_W3)                // 39002112
#define N_W4    (HDIM * OUTD)                  // 1121280
#define N_WALL  (OFF_W4 + N_W4)                // 40123392

// ---------------------------------------------------------------------------
// Scratch (static device globals; no allocation allowed)
// ---------------------------------------------------------------------------
__device__ __align__(16) float g_h [MROWS * HDIM];
__device__ __align__(16) float g_U [MROWS * 3 * HDIM];
__device__ __align__(16) __nv_bfloat16 g_xthi[MROWS * FEAD];
__device__ __align__(16) __nv_bfloat16 g_xtlo[MROWS * FEAD];
__device__ __align__(16) __nv_bfloat16 g_Ahi [MROWS * HDIM];
__device__ __align__(16) __nv_bfloat16 g_Alo [MROWS * HDIM];
__device__ __align__(16) __nv_bfloat16 g_A2hi[MROWS * HDIM];
__device__ __align__(16) __nv_bfloat16 g_A2lo[MROWS * HDIM];
__device__ __align__(16) __nv_bfloat16 g_Whi [N_WALL];
__device__ __align__(16) __nv_bfloat16 g_Wlo [N_WALL];

// ---------------------------------------------------------------------------
// PTX helpers
// ---------------------------------------------------------------------------
__device__ __forceinline__ void cpa16(void* dst, const void* src, bool pred) {
    unsigned d = (unsigned)__cvta_generic_to_shared(dst);
    if (pred) {
        asm volatile("cp.async.cg.shared.global [%0], [%1], 16;\n" :: "r"(d), "l"(src) : "memory");
    } else {
        uint4 z = {0u, 0u, 0u, 0u};
        *reinterpret_cast<uint4*>(dst) = z;
    }
}
__device__ __forceinline__ void cp_commit() { asm volatile("cp.async.commit_group;\n" ::: "memory"); }
__device__ __forceinline__ void cp_wait1()  { asm volatile("cp.async.wait_group 1;\n" ::: "memory"); }

__device__ __forceinline__ void ldsm_x4(uint32_t* r, const void* p) {
    unsigned a = (unsigned)__cvta_generic_to_shared(p);
    asm volatile("ldmatrix.sync.aligned.m8n8.x4.shared.b16 {%0,%1,%2,%3}, [%4];\n"
                 : "=r"(r[0]), "=r"(r[1]), "=r"(r[2]), "=r"(r[3]) : "r"(a));
}
__device__ __forceinline__ void ldsm_x2_t(uint32_t* r, const void* p) {
    unsigned a = (unsigned)__cvta_generic_to_shared(p);
    asm volatile("ldmatrix.sync.aligned.m8n8.x2.trans.shared.b16 {%0,%1}, [%2];\n"
                 : "=r"(r[0]), "=r"(r[1]) : "r"(a));
}
__device__ __forceinline__ void mma_bf16(float& d0, float& d1, float& d2, float& d3,
                                         const uint32_t a[4], const uint32_t b[2]) {
    asm volatile("mma.sync.aligned.m16n8k16.row.col.f32.bf16.bf16.f32 "
                 "{%0,%1,%2,%3}, {%4,%5,%6,%7}, {%8,%9}, {%0,%1,%2,%3};\n"
                 : "+f"(d0), "+f"(d1), "+f"(d2), "+f"(d3)
                 : "r"(a[0]), "r"(a[1]), "r"(a[2]), "r"(a[3]), "r"(b[0]), "r"(b[1]));
}
__device__ __forceinline__ float tanh_fast(float x) {
    float y; asm("tanh.approx.f32 %0, %1;" : "=f"(y) : "f"(x)); return y;
}
__device__ __forceinline__ float sigmoid_fast(float x) {
    return 1.0f / (1.0f + __expf(-x));
}

// ---------------------------------------------------------------------------
// Split fp32 -> bf16 hi + bf16 lo (Ootomo split). n must be multiple of 4.
// ---------------------------------------------------------------------------
__global__ void split_kernel(const float4* __restrict__ src,
                             __nv_bfloat16* __restrict__ hi,
                             __nv_bfloat16* __restrict__ lo, int n4) {
    int i = blockIdx.x * blockDim.x + threadIdx.x;
    if (i >= n4) return;
    float4 v = src[i];
    float vs[4] = {v.x, v.y, v.z, v.w};
    __nv_bfloat16 h[4], l[4];
#pragma unroll
    for (int j = 0; j < 4; j++) {
        h[j] = __float2bfloat16(vs[j]);
        l[j] = __float2bfloat16(vs[j] - __bfloat162float(h[j]));
    }
    __nv_bfloat162* hp = reinterpret_cast<__nv_bfloat162*>(hi + (size_t)i * 4);
    __nv_bfloat162* lp = reinterpret_cast<__nv_bfloat162*>(lo + (size_t)i * 4);
    hp[0] = __nv_bfloat162(h[0], h[1]);
    hp[1] = __nv_bfloat162(h[2], h[3]);
    lp[0] = __nv_bfloat162(l[0], l[1]);
    lp[1] = __nv_bfloat162(l[2], l[3]);
}

// x [B,T,FEA] -> time-major split bf16 [t*B+b, FEA]
__global__ void transpose_split_kernel(const float* __restrict__ x,
                                       __nv_bfloat16* __restrict__ hi,
                                       __nv_bfloat16* __restrict__ lo) {
    int idx = blockIdx.x * blockDim.x + threadIdx.x;
    if (idx >= MROWS * FEAD) return;
    int f = idx % FEAD;
    int m = idx / FEAD;
    int b = m % BSZ;
    int t = m / BSZ;
    float v = x[((size_t)b * TSZ + t) * FEAD + f];
    __nv_bfloat16 h = __float2bfloat16(v);
    hi[idx] = h;
    lo[idx] = __float2bfloat16(v - __bfloat162float(h));
}

// ---------------------------------------------------------------------------
// Tensor-core GEMM: C[M,N] = A[M,K] @ B[K,N] via bf16x3 (hi/lo split operands)
// Tile 64x128x16, 256 threads (8 warps = 2x4, warp tile 32x32), cp.async
// double buffering, ldmatrix fragments.
// ---------------------------------------------------------------------------
#define BM 64
#define BN 128
#define BK 16

template<int RELU, int REMAP, int WF32, int WSPLIT>
__global__ __launch_bounds__(256, 2)
void mma_gemm(const __nv_bfloat16* __restrict__ Ahi, const __nv_bfloat16* __restrict__ Alo,
              const __nv_bfloat16* __restrict__ Bhi, const __nv_bfloat16* __restrict__ Blo,
              const float* __restrict__ bias,
              float* __restrict__ Cf,
              __nv_bfloat16* __restrict__ Chi, __nv_bfloat16* __restrict__ Clo,
              int M, int K, int N) {
    __shared__ __nv_bfloat16 sAh[2][BM][24];
    __shared__ __nv_bfloat16 sAl[2][BM][24];
    __shared__ __nv_bfloat16 sBh[2][BK][136];
    __shared__ __nv_bfloat16 sBl[2][BK][136];

    const int tid  = threadIdx.x;
    const int lane = tid & 31;
    const int warp = tid >> 5;
    const int wm = warp >> 2;      // 0..1
    const int wn = warp & 3;       // 0..3
    const int row0 = blockIdx.y * BM;
    const int col0 = blockIdx.x * BN;
    const bool nAligned = ((N & 7) == 0);

    // staging mapping
    const int a_part = tid >> 7;          // 0 = hi, 1 = lo
    const int a_m    = (tid & 127) >> 1;  // 0..63
    const int a_half = tid & 1;           // 0..1 (8 bf16 each)
    const int b_kr   = tid >> 4;          // 0..15
    const int b_ch   = tid & 15;          // 0..15 (8 bf16 each)

    float acc[2][4][4];
#pragma unroll
    for (int mt = 0; mt < 2; mt++)
#pragma unroll
        for (int nt = 0; nt < 4; nt++)
#pragma unroll
            for (int j = 0; j < 4; j++) acc[mt][nt][j] = 0.0f;

    const int NTILES = (K + BK - 1) / BK;

    auto stage = [&](int k0, int buf) {
        // A tile (one 16B chunk per thread, for its part)
        {
            const __nv_bfloat16* src = a_part ? Alo : Ahi;
            __nv_bfloat16* dst = a_part ? &sAl[buf][a_m][a_half * 8]
                                        : &sAh[buf][a_m][a_half * 8];
            int gr = row0 + a_m;
            int gk = k0 + a_half * 8;
            bool p = (gr < M) && (gk < K);
            cpa16(dst, src + (size_t)gr * K + gk, p);
        }
        // B tile (two 16B chunks per thread: hi + lo)
        {
            int gk = k0 + b_kr;
            int gn = col0 + b_ch * 8;
            if (nAligned) {
                bool p = (gk < K) && (gn < N);
                cpa16(&sBh[buf][b_kr][b_ch * 8], Bhi + (size_t)gk * N + gn, p);
                cpa16(&sBl[buf][b_kr][b_ch * 8], Blo + (size_t)gk * N + gn, p);
            } else {
#pragma unroll
                for (int j = 0; j < 8; j++) {
                    int c = gn + j;
                    bool p = (gk < K) && (c < N);
                    sBh[buf][b_kr][b_ch * 8 + j] = p ? Bhi[(size_t)gk * N + c] : __nv_bfloat16(0.0f);
                    sBl[buf][b_kr][b_ch * 8 + j] = p ? Blo[(size_t)gk * N + c] : __nv_bfloat16(0.0f);
                }
            }
        }
    };

    stage(0, 0);
    cp_commit();

    for (int it = 0; it < NTILES; ++it) {
        if (it + 1 < NTILES) stage((it + 1) * BK, (it + 1) & 1);
        cp_commit();
        cp_wait1();
        __syncthreads();

        const int buf = it & 1;
        uint32_t ah[2][4], al[2][4], bh[4][2], bl[4][2];
#pragma unroll
        for (int mt = 0; mt < 2; mt++) {
            int r = wm * 32 + mt * 16 + (lane & 15);
            int kk = (lane >> 4) * 8;
            ldsm_x4(ah[mt], &sAh[buf][r][kk]);
            ldsm_x4(al[mt], &sAl[buf][r][kk]);
        }
#pragma unroll
        for (int nt = 0; nt < 4; nt++) {
            int n0 = wn * 32 + nt * 8;
            int kr = lane & 15;
            ldsm_x2_t(bh[nt], &sBh[buf][kr][n0]);
            ldsm_x2_t(bl[nt], &sBl[buf][kr][n0]);
        }
#pragma unroll
        for (int mt = 0; mt < 2; mt++) {
#pragma unroll
            for (int nt = 0; nt < 4; nt++) {
                float* d = acc[mt][nt];
                mma_bf16(d[0], d[1], d[2], d[3], ah[mt], bh[nt]);
                mma_bf16(d[0], d[1], d[2], d[3], ah[mt], bl[nt]);
                mma_bf16(d[0], d[1], d[2], d[3], al[mt], bh[nt]);
            }
        }
        __syncthreads();
    }

    // Epilogue
#pragma unroll
    for (int mt = 0; mt < 2; mt++) {
#pragma unroll
        for (int nt = 0; nt < 4; nt++) {
            int rbase = row0 + wm * 32 + mt * 16 + (lane >> 2);
            int cbase = col0 + wn * 32 + nt * 8 + ((lane & 3) << 1);
#pragma unroll
            for (int half = 0; half < 2; half++) {
                int row = rbase + half * 8;
                if (row >= M) continue;
                int orow = row;
                if (REMAP) {
                    int bb = row % BSZ;
                    int tt = row / BSZ;
                    orow = bb * TSZ + tt;
                }
#pragma unroll
                for (int j = 0; j < 2; j++) {
                    int col = cbase + j;
                    if (col >= N) continue;
                    float v = acc[mt][nt][half * 2 + j];
                    if (bias) v += bias[col];
                    if (RELU) v = fmaxf(v, 0.0f);
                    size_t o = (size_t)orow * N + col;
                    if (WF32) Cf[o] = v;
                    if (WSPLIT) {
                        __nv_bfloat16 h = __float2bfloat16(v);
                        Chi[o] = h;
                        Clo[o] = __float2bfloat16(v - __bfloat162float(h));
                    }
                }
            }
        }
    }
}

// ---------------------------------------------------------------------------
// SRU recurrence. One thread per (b, h); chunked prefetch for MLP.
// Updates h in place (fp32) + writes bf16 hi/lo split for next GEMM.
// ---------------------------------------------------------------------------
__global__ __launch_bounds__(128)
void sru_scan_kernel(const float* __restrict__ U, const float* __restrict__ c0,
                     const float* __restrict__ sb, float* __restrict__ h,
                     __nv_bfloat16* __restrict__ Ahi, __nv_bfloat16* __restrict__ Alo,
                     float* __restrict__ c_out) {
    int idx = blockIdx.x * 128 + threadIdx.x;
    if (idx >= BSZ * HDIM) return;
    int hh = idx & (HDIM - 1);
    int b  = idx >> 10;
    float c  = c0[idx];
    float bf = sb[hh];
    float br = sb[HDIM + hh];
#pragma unroll
    for (int t0 = 0; t0 < TSZ; t0 += 5) {
        float xf[5], uf[5], ur[5], hv[5];
#pragma unroll
        for (int i = 0; i < 5; i++) {
            int row = (t0 + i) * BSZ + b;
            const float* Ur = U + (size_t)row * (3 * HDIM);
            xf[i] = Ur[hh];
            uf[i] = Ur[HDIM + hh];
            ur[i] = Ur[2 * HDIM + hh];
            hv[i] = h[(size_t)row * HDIM + hh];
        }
#pragma unroll
        for (int i = 0; i < 5; i++) {
            float f = sigmoid_fast(uf[i] + bf);
            float r = sigmoid_fast(ur[i] + br);
            c = f * c + (1.0f - f) * xf[i];
            float hn = r * tanh_fast(c) + (1.0f - r) * hv[i];
            size_t o = (size_t)((t0 + i) * BSZ + b) * HDIM + hh;
            h[o] = hn;
            __nv_bfloat16 hb = __float2bfloat16(hn);
            Ahi[o] = hb;
            Alo[o] = __float2bfloat16(hn - __bfloat162float(hb));
        }
    }
    c_out[idx] = c;
}

// ---------------------------------------------------------------------------
extern "C" void kernel_launch(void* const* d_in, const int* in_sizes, int n_in,
                              void* d_out, int out_size) {
    const float* x      = (const float*)d_in[0];
    const float* hidden = (const float*)d_in[1];
    const float* W1     = (const float*)d_in[2];
    const float* b1     = (const float*)d_in[3];
    const float* sru_W  = (const float*)d_in[4];
    const float* sru_b  = (const float*)d_in[5];
    const float* W3     = (const float*)d_in[6];
    const float* b3     = (const float*)d_in[7];
    const float* W4     = (const float*)d_in[8];
    const float* b4     = (const float*)d_in[9];
    float* out = (float*)d_out;

    float *h, *U;
    __nv_bfloat16 *xthi, *xtlo, *Ahi, *Alo, *A2hi, *A2lo, *Whi, *Wlo;
    cudaGetSymbolAddress((void**)&h,    g_h);
    cudaGetSymbolAddress((void**)&U,    g_U);
    cudaGetSymbolAddress((void**)&xthi, g_xthi);
    cudaGetSymbolAddress((void**)&xtlo, g_xtlo);
    cudaGetSymbolAddress((void**)&Ahi,  g_Ahi);
    cudaGetSymbolAddress((void**)&Alo,  g_Alo);
    cudaGetSymbolAddress((void**)&A2hi, g_A2hi);
    cudaGetSymbolAddress((void**)&A2lo, g_A2lo);
    cudaGetSymbolAddress((void**)&Whi,  g_Whi);
    cudaGetSymbolAddress((void**)&Wlo,  g_Wlo);

    // Input transpose + split; weight splits (recomputed every call: deterministic)
    transpose_split_kernel<<<(MROWS * FEAD + 255) / 256, 256>>>(x, xthi, xtlo);
    split_kernel<<<(N_W1 / 4 + 255) / 256, 256>>>((const float4*)W1,    Whi + OFF_W1,  Wlo + OFF_W1,  N_W1 / 4);
    split_kernel<<<(N_SRU / 4 + 255) / 256, 256>>>((const float4*)sru_W, Whi + OFF_SRU, Wlo + OFF_SRU, N_SRU / 4);
    split_kernel<<<(N_W3 / 4 + 255) / 256, 256>>>((const float4*)W3,    Whi + OFF_W3,  Wlo + OFF_W3,  N_W3 / 4);
    split_kernel<<<(N_W4 / 4 + 255) / 256, 256>>>((const float4*)W4,    Whi + OFF_W4,  Wlo + OFF_W4,  N_W4 / 4);

    const int GY = (MROWS + BM - 1) / BM;  // 13

    // Dense layer 1: h = xt @ W1 + b1 (write fp32 + split)
    {
        dim3 grid((HDIM + BN - 1) / BN, GY);
        mma_gemm<0, 0, 1, 1><<<grid, 256>>>(xthi, xtlo, Whi + OFF_W1, Wlo + OFF_W1,
                                            b1, h, Ahi, Alo, MROWS, FEAD, HDIM);
    }

    // SRU layers
    for (int l = 0; l < LNUM; l++) {
        dim3 gridU((3 * HDIM + BN - 1) / BN, GY);  // 24 x 13
        size_t woff = OFF_SRU + (size_t)l * HDIM * 3 * HDIM;
        mma_gemm<0, 0, 1, 0><<<gridU, 256>>>(Ahi, Alo, Whi + woff, Wlo + woff,
                                             nullptr, U, nullptr, nullptr,
                                             MROWS, HDIM, 3 * HDIM);
        sru_scan_kernel<<<(BSZ * HDIM + 127) / 128, 128>>>(
            U, hidden + (size_t)l * BSZ * HDIM, sru_b + (size_t)l * 2 * HDIM,
            h, Ahi, Alo, out + OUT_ELEMS + (size_t)l * BSZ * HDIM);
    }

    // Dense ReLU with time-major -> batch-major row remap (write split only)
    {
        dim3 grid((HDIM + BN - 1) / BN, GY);
        mma_gemm<1, 1, 0, 1><<<grid, 256>>>(Ahi, Alo, Whi + OFF_W3, Wlo + OFF_W3,
                                            b3, nullptr, A2hi, A2lo, MROWS, HDIM, HDIM);
    }

    // Output projection (fp32 out)
    {
        dim3 grid((OUTD + BN - 1) / BN, GY);  // 9 x 13
        mma_gemm<0, 0, 1, 0><<<grid, 256>>>(A2hi, A2lo, Whi + OFF_W4, Wlo + OFF_W4,
                                            b4, out, nullptr, nullptr, MROWS, HDIM, OUTD);
    }
}

// round 10
// speedup vs baseline: 2.7163x; 1.1746x over previous
#include <cuda_runtime.h>
#include <cuda_bf16.h>
#include <cstdint>
#include <cstddef>

#define BSZ   40
#define TSZ   20
#define FEAD  200
#define HDIM  1024
#define OUTD  1095
#define LNUM  12
#define MROWS (BSZ * TSZ)          // 800
#define MPAD  896                  // 7 * 128 (A buffer padded so tile loads stay in-bounds)
#define OUT_ELEMS (MROWS * OUTD)   // 876000

#define OFF_W1  0
#define N_W1    (FEAD * HDIM)
#define OFF_W3  (OFF_W1 + N_W1)
#define N_W3    (HDIM * HDIM)
#define OFF_W4  (OFF_W3 + N_W3)
#define N_W4    (HDIM * OUTD)
#define N_WSM   (OFF_W4 + N_W4)
#define N_SRU   (LNUM * HDIM * 3 * HDIM)

// ---------------------------------------------------------------------------
// Scratch
// ---------------------------------------------------------------------------
__device__ __align__(16) float g_h [MROWS * HDIM];
__device__ __align__(16) float g_U [MROWS * 3 * HDIM];
__device__ __align__(16) __nv_bfloat16 g_xthi[MROWS * FEAD];
__device__ __align__(16) __nv_bfloat16 g_xtlo[MROWS * FEAD];
__device__ __align__(16) __nv_bfloat16 g_Ahi [MPAD * HDIM];
__device__ __align__(16) __nv_bfloat16 g_Alo [MPAD * HDIM];
__device__ __align__(16) __nv_bfloat16 g_A2hi[MROWS * HDIM];
__device__ __align__(16) __nv_bfloat16 g_A2lo[MROWS * HDIM];
__device__ __align__(16) __nv_bfloat16 g_Wsmhi[N_WSM];
__device__ __align__(16) __nv_bfloat16 g_Wsmlo[N_WSM];
__device__ __align__(16) __nv_bfloat16 g_Wshi[N_SRU];   // sru_W split, native [K,3H] layout
__device__ __align__(16) __nv_bfloat16 g_Wslo[N_SRU];

// ---------------------------------------------------------------------------
// PTX helpers
// ---------------------------------------------------------------------------
__device__ __forceinline__ void cpa16(void* dst, const void* src, bool pred) {
    unsigned d = (unsigned)__cvta_generic_to_shared(dst);
    if (pred) {
        asm volatile("cp.async.cg.shared.global [%0], [%1], 16;\n" :: "r"(d), "l"(src) : "memory");
    } else {
        uint4 z = {0u, 0u, 0u, 0u};
        *reinterpret_cast<uint4*>(dst) = z;
    }
}
__device__ __forceinline__ void cpa16s(uint32_t daddr, const void* src) {
    asm volatile("cp.async.cg.shared.global [%0], [%1], 16;\n" :: "r"(daddr), "l"(src) : "memory");
}
__device__ __forceinline__ void cp_commit() { asm volatile("cp.async.commit_group;\n" ::: "memory"); }
__device__ __forceinline__ void cp_wait1()  { asm volatile("cp.async.wait_group 1;\n" ::: "memory"); }
__device__ __forceinline__ void cp_wait0()  { asm volatile("cp.async.wait_group 0;\n" ::: "memory"); }

__device__ __forceinline__ void ldsm_x4(uint32_t* r, uint32_t a) {
    asm volatile("ldmatrix.sync.aligned.m8n8.x4.shared.b16 {%0,%1,%2,%3}, [%4];\n"
                 : "=r"(r[0]), "=r"(r[1]), "=r"(r[2]), "=r"(r[3]) : "r"(a));
}
__device__ __forceinline__ void ldsm_x4_p(uint32_t* r, const void* p) {
    unsigned a = (unsigned)__cvta_generic_to_shared(p);
    ldsm_x4(r, a);
}
__device__ __forceinline__ void ldsm_x4_t(uint32_t* r, uint32_t a) {
    asm volatile("ldmatrix.sync.aligned.m8n8.x4.trans.shared.b16 {%0,%1,%2,%3}, [%4];\n"
                 : "=r"(r[0]), "=r"(r[1]), "=r"(r[2]), "=r"(r[3]) : "r"(a));
}
__device__ __forceinline__ void ldsm_x2_t(uint32_t* r, const void* p) {
    unsigned a = (unsigned)__cvta_generic_to_shared(p);
    asm volatile("ldmatrix.sync.aligned.m8n8.x2.trans.shared.b16 {%0,%1}, [%2];\n"
                 : "=r"(r[0]), "=r"(r[1]) : "r"(a));
}
__device__ __forceinline__ void mma_bf16(float& d0, float& d1, float& d2, float& d3,
                                         const uint32_t a[4], const uint32_t b[2]) {
    asm volatile("mma.sync.aligned.m16n8k16.row.col.f32.bf16.bf16.f32 "
                 "{%0,%1,%2,%3}, {%4,%5,%6,%7}, {%8,%9}, {%0,%1,%2,%3};\n"
                 : "+f"(d0), "+f"(d1), "+f"(d2), "+f"(d3)
                 : "r"(a[0]), "r"(a[1]), "r"(a[2]), "r"(a[3]), "r"(b[0]), "r"(b[1]));
}
__device__ __forceinline__ float tanh_fast(float x) {
    float y; asm("tanh.approx.f32 %0, %1;" : "=f"(y) : "f"(x)); return y;
}
__device__ __forceinline__ float sigmoid_fast(float x) {
    return 1.0f / (1.0f + __expf(-x));
}

// ---------------------------------------------------------------------------
// Preprocessing
// ---------------------------------------------------------------------------
__device__ __forceinline__ uint32_t pack2bf(float a, float b) {
    __nv_bfloat162 v(__float2bfloat16(a), __float2bfloat16(b));
    return *reinterpret_cast<uint32_t*>(&v);
}

// 8 floats per thread -> 8 bf16 hi (16B) + 8 bf16 lo (16B)
__global__ void split8_kernel(const float4* __restrict__ src,
                              uint4* __restrict__ hi, uint4* __restrict__ lo, int n8) {
    int i = blockIdx.x * blockDim.x + threadIdx.x;
    if (i >= n8) return;
    float4 a = src[2 * i];
    float4 b = src[2 * i + 1];
    float v[8] = {a.x, a.y, a.z, a.w, b.x, b.y, b.z, b.w};
    float hv[8], lv[8];
#pragma unroll
    for (int j = 0; j < 8; j++) {
        hv[j] = __bfloat162float(__float2bfloat16(v[j]));
        lv[j] = v[j] - hv[j];
    }
    uint4 H, L;
    H.x = pack2bf(hv[0], hv[1]); H.y = pack2bf(hv[2], hv[3]);
    H.z = pack2bf(hv[4], hv[5]); H.w = pack2bf(hv[6], hv[7]);
    L.x = pack2bf(lv[0], lv[1]); L.y = pack2bf(lv[2], lv[3]);
    L.z = pack2bf(lv[4], lv[5]); L.w = pack2bf(lv[6], lv[7]);
    hi[i] = H;
    lo[i] = L;
}

__global__ void transpose_split_kernel(const float* __restrict__ x,
                                       __nv_bfloat16* __restrict__ hi,
                                       __nv_bfloat16* __restrict__ lo) {
    int idx = blockIdx.x * blockDim.x + threadIdx.x;
    if (idx >= MROWS * FEAD) return;
    int f = idx % FEAD;
    int m = idx / FEAD;
    int b = m % BSZ;
    int t = m / BSZ;
    float v = x[((size_t)b * TSZ + t) * FEAD + f];
    __nv_bfloat16 h = __float2bfloat16(v);
    hi[idx] = h;
    lo[idx] = __float2bfloat16(v - __bfloat162float(h));
}

__global__ void zeropad_kernel(__nv_bfloat16* __restrict__ hi, __nv_bfloat16* __restrict__ lo) {
    int i = blockIdx.x * blockDim.x + threadIdx.x;
    int n = (MPAD - MROWS) * HDIM / 2;
    if (i >= n) return;
    reinterpret_cast<uint32_t*>(hi + (size_t)MROWS * HDIM)[i] = 0u;
    reinterpret_cast<uint32_t*>(lo + (size_t)MROWS * HDIM)[i] = 0u;
}

// ---------------------------------------------------------------------------
// U-GEMM (mma.sync, bf16x3):  U[800, 3072] = A[.,1024] @ W[1024, 3072]
// BM=128, BN=192, BK=32, 384 threads (12 warps = 4x3, warp tile 32x64).
// Grid (16, 7) = 112 blocks -> single wave on 148 SMs.
// ---------------------------------------------------------------------------
#define UK   1024
#define UN   3072
#define UBM  128
#define UBN  192
#define UBK  32
#define UNIT (UK / UBK)          // 32 iters
// dynamic smem layout (bytes)
#define UA_PB   (UBM * 40 * 2)   // per part per buf: 128 rows x 40 bf16 = 10240
#define UB_PB   (UBK * 200 * 2)  // per part per buf: 32 rows x 200 bf16 = 12800
#define U_SM_AH 0
#define U_SM_AL (U_SM_AH + 2 * UA_PB)      // 20480
#define U_SM_BH (U_SM_AL + 2 * UA_PB)      // 40960
#define U_SM_BL (U_SM_BH + 2 * UB_PB)      // 66560
#define U_SM_TOTAL (U_SM_BL + 2 * UB_PB)   // 92160

__global__ __launch_bounds__(384, 1)
void u_gemm_kernel(const __nv_bfloat16* __restrict__ Ahi,
                   const __nv_bfloat16* __restrict__ Alo,
                   const __nv_bfloat16* __restrict__ Bhi,
                   const __nv_bfloat16* __restrict__ Blo,
                   float* __restrict__ U) {
    extern __shared__ char dsm[];
    uint32_t smem;
    asm("{ .reg .u64 t; cvta.to.shared.u64 t, %1; cvt.u32.u64 %0, t; }"
        : "=r"(smem) : "l"(dsm));

    const int tid  = threadIdx.x;
    const int warp = tid >> 5;
    const int lane = tid & 31;
    const int wm = warp >> 2;          // 0..2  -> but need 4 rows x 3 cols:
    // use warp / 3 and warp % 3 instead:
    const int wrow = warp / 3;         // 0..3  (m)
    const int wcol = warp % 3;         // 0..2  (n)
    const int row0 = blockIdx.y * UBM;
    const int col0 = blockIdx.x * UBN;
    (void)wm;

    float acc[2][4][2][4];
#pragma unroll
    for (int a = 0; a < 2; a++)
#pragma unroll
        for (int b = 0; b < 4; b++)
#pragma unroll
            for (int c = 0; c < 2; c++)
#pragma unroll
                for (int d = 0; d < 4; d++) acc[a][b][c][d] = 0.0f;

    auto stage = [&](int it, int buf) {
        const int k0 = it * UBK;
        // A: 1024 16B-chunks (hi 512 + lo 512). chunk: row = c>>2, kc = c&3
#pragma unroll
        for (int i = 0; i < 3; i++) {
            int idx = tid + i * 384;
            if (idx < 1024) {
                int part = idx >> 9;
                int c = idx & 511;
                int r = c >> 2, kc = c & 3;
                uint32_t daddr = smem + (part ? U_SM_AL : U_SM_AH) + buf * UA_PB
                               + r * 80 + kc * 16;
                const __nv_bfloat16* src = part ? Alo : Ahi;
                cpa16s(daddr, src + (size_t)(row0 + r) * UK + k0 + kc * 8);
            }
        }
        // B: 1536 chunks (hi 768 + lo 768). chunk: row = c/24, nc = c%24
#pragma unroll
        for (int i = 0; i < 4; i++) {
            int idx = tid + i * 384;
            int part = idx >= 768;
            int c = part ? idx - 768 : idx;
            int r = c / 24, nc = c % 24;
            uint32_t daddr = smem + (part ? U_SM_BL : U_SM_BH) + buf * UB_PB
                           + r * 400 + nc * 16;
            const __nv_bfloat16* src = part ? Blo : Bhi;
            cpa16s(daddr, src + (size_t)(k0 + r) * UN + col0 + nc * 8);
        }
    };

    stage(0, 0);
    cp_commit();

    for (int it = 0; it < UNIT; ++it) {
        if (it + 1 < UNIT) {
            stage(it + 1, (it + 1) & 1);
            cp_commit();
            cp_wait1();
        } else {
            cp_wait0();
        }
        __syncthreads();
        const int buf = it & 1;

#pragma unroll
        for (int kk = 0; kk < 2; kk++) {   // two k16 halves of BK=32
            uint32_t ah[2][4], al[2][4], bh[4][4], bl[4][4];
            // A frags
#pragma unroll
            for (int mt = 0; mt < 2; mt++) {
                uint32_t off = (uint32_t)((wrow * 32 + mt * 16 + (lane & 15)) * 80
                             + (kk * 16 + ((lane >> 4) << 3)) * 2) + buf * UA_PB;
                ldsm_x4(ah[mt], smem + U_SM_AH + off);
                ldsm_x4(al[mt], smem + U_SM_AL + off);
            }
            // B frags (trans): lanes 0-15 -> rows k..k+15 @ n0; lanes 16-31 -> @ n0+8
#pragma unroll
            for (int nt = 0; nt < 4; nt++) {
                uint32_t off = (uint32_t)((kk * 16 + (lane & 15)) * 400
                             + (wcol * 64 + nt * 16 + ((lane >> 4) << 3)) * 2) + buf * UB_PB;
                ldsm_x4_t(bh[nt], smem + U_SM_BH + off);
                ldsm_x4_t(bl[nt], smem + U_SM_BL + off);
            }
            // MMAs: 2 mt x 4 nt x 2 n8 x 3 terms = 48
#pragma unroll
            for (int mt = 0; mt < 2; mt++) {
#pragma unroll
                for (int nt = 0; nt < 4; nt++) {
#pragma unroll
                    for (int h8 = 0; h8 < 2; h8++) {
                        float* d = acc[mt][nt][h8];
                        mma_bf16(d[0], d[1], d[2], d[3], ah[mt], &bh[nt][h8 * 2]);
                        mma_bf16(d[0], d[1], d[2], d[3], ah[mt], &bl[nt][h8 * 2]);
                        mma_bf16(d[0], d[1], d[2], d[3], al[mt], &bh[nt][h8 * 2]);
                    }
                }
            }
        }
        __syncthreads();
    }

    // Epilogue: fp32 stores, rows < 800 only
#pragma unroll
    for (int mt = 0; mt < 2; mt++) {
#pragma unroll
        for (int half = 0; half < 2; half++) {
            int row = row0 + wrow * 32 + mt * 16 + (lane >> 2) + half * 8;
            if (row >= MROWS) continue;
            float* dst = U + (size_t)row * UN;
#pragma unroll
            for (int nt = 0; nt < 4; nt++) {
#pragma unroll
                for (int h8 = 0; h8 < 2; h8++) {
                    int col = col0 + wcol * 64 + nt * 16 + h8 * 8 + ((lane & 3) << 1);
                    float2 v;
                    v.x = acc[mt][nt][h8][half * 2 + 0];
                    v.y = acc[mt][nt][h8][half * 2 + 1];
                    *reinterpret_cast<float2*>(dst + col) = v;
                }
            }
        }
    }
}

// ---------------------------------------------------------------------------
// mma.sync GEMM for dense layers (from R4, unchanged)
// ---------------------------------------------------------------------------
#define BM 64
#define BN 128
#define BK 16

template<int RELU, int REMAP, int WF32, int WSPLIT>
__global__ __launch_bounds__(256, 2)
void mma_gemm(const __nv_bfloat16* __restrict__ Ahi, const __nv_bfloat16* __restrict__ Alo,
              const __nv_bfloat16* __restrict__ Bhi, const __nv_bfloat16* __restrict__ Blo,
              const float* __restrict__ bias,
              float* __restrict__ Cf,
              __nv_bfloat16* __restrict__ Chi, __nv_bfloat16* __restrict__ Clo,
              int M, int K, int N) {
    __shared__ __nv_bfloat16 sAh[2][BM][24];
    __shared__ __nv_bfloat16 sAl[2][BM][24];
    __shared__ __nv_bfloat16 sBh[2][BK][136];
    __shared__ __nv_bfloat16 sBl[2][BK][136];

    const int tid  = threadIdx.x;
    const int lane = tid & 31;
    const int warp = tid >> 5;
    const int wm = warp >> 2;
    const int wn = warp & 3;
    const int row0 = blockIdx.y * BM;
    const int col0 = blockIdx.x * BN;
    const bool nAligned = ((N & 7) == 0);

    const int a_part = tid >> 7;
    const int a_m    = (tid & 127) >> 1;
    const int a_half = tid & 1;
    const int b_kr   = tid >> 4;
    const int b_ch   = tid & 15;

    float acc[2][4][4];
#pragma unroll
    for (int mt = 0; mt < 2; mt++)
#pragma unroll
        for (int nt = 0; nt < 4; nt++)
#pragma unroll
            for (int j = 0; j < 4; j++) acc[mt][nt][j] = 0.0f;

    const int NTILES = (K + BK - 1) / BK;

    auto stage = [&](int k0, int buf) {
        {
            const __nv_bfloat16* src = a_part ? Alo : Ahi;
            __nv_bfloat16* dst = a_part ? &sAl[buf][a_m][a_half * 8]
                                        : &sAh[buf][a_m][a_half * 8];
            int gr = row0 + a_m;
            int gk = k0 + a_half * 8;
            bool p = (gr < M) && (gk < K);
            cpa16(dst, src + (size_t)gr * K + gk, p);
        }
        {
            int gk = k0 + b_kr;
            int gn = col0 + b_ch * 8;
            if (nAligned) {
                bool p = (gk < K) && (gn < N);
                cpa16(&sBh[buf][b_kr][b_ch * 8], Bhi + (size_t)gk * N + gn, p);
                cpa16(&sBl[buf][b_kr][b_ch * 8], Blo + (size_t)gk * N + gn, p);
            } else {
#pragma unroll
                for (int j = 0; j < 8; j++) {
                    int c = gn + j;
                    bool p = (gk < K) && (c < N);
                    sBh[buf][b_kr][b_ch * 8 + j] = p ? Bhi[(size_t)gk * N + c] : __nv_bfloat16(0.0f);
                    sBl[buf][b_kr][b_ch * 8 + j] = p ? Blo[(size_t)gk * N + c] : __nv_bfloat16(0.0f);
                }
            }
        }
    };

    stage(0, 0);
    cp_commit();

    for (int it = 0; it < NTILES; ++it) {
        if (it + 1 < NTILES) stage((it + 1) * BK, (it + 1) & 1);
        cp_commit();
        cp_wait1();
        __syncthreads();

        const int buf = it & 1;
        uint32_t ah[2][4], al[2][4], bh[4][2], bl[4][2];
#pragma unroll
        for (int mt = 0; mt < 2; mt++) {
            int r = wm * 32 + mt * 16 + (lane & 15);
            int kk = (lane >> 4) * 8;
            ldsm_x4_p(ah[mt], &sAh[buf][r][kk]);
            ldsm_x4_p(al[mt], &sAl[buf][r][kk]);
        }
#pragma unroll
        for (int nt = 0; nt < 4; nt++) {
            int n0 = wn * 32 + nt * 8;
            int kr = lane & 15;
            ldsm_x2_t(bh[nt], &sBh[buf][kr][n0]);
            ldsm_x2_t(bl[nt], &sBl[buf][kr][n0]);
        }
#pragma unroll
        for (int mt = 0; mt < 2; mt++) {
#pragma unroll
            for (int nt = 0; nt < 4; nt++) {
                float* d = acc[mt][nt];
                mma_bf16(d[0], d[1], d[2], d[3], ah[mt], bh[nt]);
                mma_bf16(d[0], d[1], d[2], d[3], ah[mt], bl[nt]);
                mma_bf16(d[0], d[1], d[2], d[3], al[mt], bh[nt]);
            }
        }
        __syncthreads();
    }

#pragma unroll
    for (int mt = 0; mt < 2; mt++) {
#pragma unroll
        for (int nt = 0; nt < 4; nt++) {
            int rbase = row0 + wm * 32 + mt * 16 + (lane >> 2);
            int cbase = col0 + wn * 32 + nt * 8 + ((lane & 3) << 1);
#pragma unroll
            for (int half = 0; half < 2; half++) {
                int row = rbase + half * 8;
                if (row >= M) continue;
                int orow = row;
                if (REMAP) {
                    int bb = row % BSZ;
                    int tt = row / BSZ;
                    orow = bb * TSZ + tt;
                }
#pragma unroll
                for (int j = 0; j < 2; j++) {
                    int col = cbase + j;
                    if (col >= N) continue;
                    float v = acc[mt][nt][half * 2 + j];
                    if (bias) v += bias[col];
                    if (RELU) v = fmaxf(v, 0.0f);
                    size_t o = (size_t)orow * N + col;
                    if (WF32) Cf[o] = v;
                    if (WSPLIT) {
                        __nv_bfloat16 h = __float2bfloat16(v);
                        Chi[o] = h;
                        Clo[o] = __float2bfloat16(v - __bfloat162float(h));
                    }
                }
            }
        }
    }
}

// ---------------------------------------------------------------------------
// SRU recurrence (from R4)
// ---------------------------------------------------------------------------
__global__ __launch_bounds__(128)
void sru_scan_kernel(const float* __restrict__ U, const float* __restrict__ c0,
                     const float* __restrict__ sb, float* __restrict__ h,
                     __nv_bfloat16* __restrict__ Ahi, __nv_bfloat16* __restrict__ Alo,
                     float* __restrict__ c_out) {
    int idx = blockIdx.x * 128 + threadIdx.x;
    if (idx >= BSZ * HDIM) return;
    int hh = idx & (HDIM - 1);
    int b  = idx >> 10;
    float c  = c0[idx];
    float bf = sb[hh];
    float br = sb[HDIM + hh];
#pragma unroll
    for (int t0 = 0; t0 < TSZ; t0 += 5) {
        float xf[5], uf[5], ur[5], hv[5];
#pragma unroll
        for (int i = 0; i < 5; i++) {
            int row = (t0 + i) * BSZ + b;
            const float* Ur = U + (size_t)row * (3 * HDIM);
            xf[i] = Ur[hh];
            uf[i] = Ur[HDIM + hh];
            ur[i] = Ur[2 * HDIM + hh];
            hv[i] = h[(size_t)row * HDIM + hh];
        }
#pragma unroll
        for (int i = 0; i < 5; i++) {
            float f = sigmoid_fast(uf[i] + bf);
            float r = sigmoid_fast(ur[i] + br);
            c = f * c + (1.0f - f) * xf[i];
            float hn = r * tanh_fast(c) + (1.0f - r) * hv[i];
            size_t o = (size_t)((t0 + i) * BSZ + b) * HDIM + hh;
            h[o] = hn;
            __nv_bfloat16 hb = __float2bfloat16(hn);
            Ahi[o] = hb;
            Alo[o] = __float2bfloat16(hn - __bfloat162float(hb));
        }
    }
    c_out[idx] = c;
}

// ---------------------------------------------------------------------------
extern "C" void kernel_launch(void* const* d_in, const int* in_sizes, int n_in,
                              void* d_out, int out_size) {
    const float* x      = (const float*)d_in[0];
    const float* hidden = (const float*)d_in[1];
    const float* W1     = (const float*)d_in[2];
    const float* b1     = (const float*)d_in[3];
    const float* sru_W  = (const float*)d_in[4];
    const float* sru_b  = (const float*)d_in[5];
    const float* W3     = (const float*)d_in[6];
    const float* b3     = (const float*)d_in[7];
    const float* W4     = (const float*)d_in[8];
    const float* b4     = (const float*)d_in[9];
    float* out = (float*)d_out;

    float *h, *U;
    __nv_bfloat16 *xthi, *xtlo, *Ahi, *Alo, *A2hi, *A2lo, *Wsmhi, *Wsmlo, *Wshi, *Wslo;
    cudaGetSymbolAddress((void**)&h,    g_h);
    cudaGetSymbolAddress((void**)&U,    g_U);
    cudaGetSymbolAddress((void**)&xthi, g_xthi);
    cudaGetSymbolAddress((void**)&xtlo, g_xtlo);
    cudaGetSymbolAddress((void**)&Ahi,  g_Ahi);
    cudaGetSymbolAddress((void**)&Alo,  g_Alo);
    cudaGetSymbolAddress((void**)&A2hi, g_A2hi);
    cudaGetSymbolAddress((void**)&A2lo, g_A2lo);
    cudaGetSymbolAddress((void**)&Wsmhi, g_Wsmhi);
    cudaGetSymbolAddress((void**)&Wsmlo, g_Wsmlo);
    cudaGetSymbolAddress((void**)&Wshi, g_Wshi);
    cudaGetSymbolAddress((void**)&Wslo, g_Wslo);

    cudaFuncSetAttribute(u_gemm_kernel,
                         cudaFuncAttributeMaxDynamicSharedMemorySize, U_SM_TOTAL);

    // Preprocessing (per-call; deterministic)
    transpose_split_kernel<<<(MROWS * FEAD + 255) / 256, 256>>>(x, xthi, xtlo);
    split8_kernel<<<(N_W1 / 8 + 255) / 256, 256>>>((const float4*)W1, (uint4*)(Wsmhi + OFF_W1), (uint4*)(Wsmlo + OFF_W1), N_W1 / 8);
    split8_kernel<<<(N_W3 / 8 + 255) / 256, 256>>>((const float4*)W3, (uint4*)(Wsmhi + OFF_W3), (uint4*)(Wsmlo + OFF_W3), N_W3 / 8);
    split8_kernel<<<(N_W4 / 8 + 255) / 256, 256>>>((const float4*)W4, (uint4*)(Wsmhi + OFF_W4), (uint4*)(Wsmlo + OFF_W4), N_W4 / 8);
    split8_kernel<<<(N_SRU / 8 + 255) / 256, 256>>>((const float4*)sru_W, (uint4*)Wshi, (uint4*)Wslo, N_SRU / 8);
    zeropad_kernel<<<((MPAD - MROWS) * HDIM / 2 + 255) / 256, 256>>>(Ahi, Alo);

    const int GY = (MROWS + BM - 1) / BM;

    // Dense layer 1: h = xt @ W1 + b1 (fp32 out + bf16 split for next GEMM)
    {
        dim3 grid((HDIM + BN - 1) / BN, GY);
        mma_gemm<0, 0, 1, 1><<<grid, 256>>>(xthi, xtlo, Wsmhi + OFF_W1, Wsmlo + OFF_W1,
                                            b1, h, Ahi, Alo, MROWS, FEAD, HDIM);
    }

    // SRU layers: big-tile U-GEMM + scan
    for (int l = 0; l < LNUM; l++) {
        size_t woff = (size_t)l * HDIM * 3 * HDIM;
        dim3 gridU(UN / UBN, MPAD / UBM);   // 16 x 7 = 112 blocks
        u_gemm_kernel<<<gridU, 384, U_SM_TOTAL>>>(Ahi, Alo, Wshi + woff, Wslo + woff, U);
        sru_scan_kernel<<<(BSZ * HDIM + 127) / 128, 128>>>(
            U, hidden + (size_t)l * BSZ * HDIM, sru_b + (size_t)l * 2 * HDIM,
            h, Ahi, Alo, out + OUT_ELEMS + (size_t)l * BSZ * HDIM);
    }

    // Dense ReLU with time-major -> batch-major row remap
    {
        dim3 grid((HDIM + BN - 1) / BN, GY);
        mma_gemm<1, 1, 0, 1><<<grid, 256>>>(Ahi, Alo, Wsmhi + OFF_W3, Wsmlo + OFF_W3,
                                            b3, nullptr, A2hi, A2lo, MROWS, HDIM, HDIM);
    }

    // Output projection
    {
        dim3 grid((OUTD + BN - 1) / BN, GY);
        mma_gemm<0, 0, 1, 0><<<grid, 256>>>(A2hi, A2lo, Wsmhi + OFF_W4, Wsmlo + OFF_W4,
                                            b4, out, nullptr, nullptr, MROWS, HDIM, OUTD);
    }
}